// round 12
// baseline (speedup 1.0000x reference)
#include <cuda_runtime.h>

#define DD     10000   // hypervector dimensions
#define TT     128     // time steps
#define CC     32      // channels
#define BB     4       // batch
#define NCLS   10
#define NWIN   125     // T - NGRAM + 1
#define TD     125     // d-tile per block (DD/TD = 80 exactly)
#define NTILES 80
#define NBLK   (NTILES * BB)   // 320
#define CSTR   33      // words per column (32 data + 1 pad; 33 % 32 == 1 -> conflict-free)

// Scratch (device globals — no allocation allowed; zero-initialized at load)
__device__ float    g_partial[BB * NTILES * NCLS];
__device__ unsigned g_ticket;

// ---------------------------------------------------------------------------
// Fused kernel, 512 threads = 16 warps: col = tid&127, q = tid>>7 (t-quarter).
// Samples tile is COLUMN-MAJOR WORD-PACKED: ssw[col*33 + w], bytes u of word w
// hold sample t = 4w+u for that column. All smem access is 32-bit and
// conflict-free (stride 33) — removes the 4-way byte-access conflicts that
// bound R6/R10 on the smem crossbar.
//  Pre  : per-thread timestamp sign bits packed into one uint (MLP=32);
//         <=3 classify weights preloaded (class split 3/3/3/1 over q).
//  Setup: q==0 warps build packed per-t histograms; q==1 packs signal signs.
//  A    : thread (col,q) computes t = [32q,32q+32) via dp4a, packs 4 samples
//         per word -> 8 conflict-free STS.32.
//  B    : windows in groups of 4: rolling word loads per neighbor column,
//         funnel-shift align, signed-byte extract, int32-exact products.
//         Split 32/32/32/29 over q (guard i < 125).
//  C    : all 16 warps: combine quarters, hard-quantize, fold +-classify_w.
//  Tail : last block (ticket) reduces 80 tile partials in fixed order.
// ---------------------------------------------------------------------------
__global__ __launch_bounds__(512) void k_fused(
    const float* __restrict__ x,
    const float* __restrict__ signals_w,
    const float* __restrict__ timestamps_w,
    const float* __restrict__ classify_w,
    float* __restrict__ out)
{
    __shared__ __align__(16) unsigned cnt_s[TT * 8];   // 4 KB packed histograms
    __shared__ int sw_s[6][128];                       // 3 KB packed signal signs
    __shared__ unsigned ssw[128 * CSTR];               // 16.9 KB word-packed samples
    __shared__ int   acc_s[4][128];                    // window-quarter partials
    __shared__ float wsum2[NCLS][4];                   // per-(class, col-group)
    __shared__ int   last_flag;

    const int tid  = threadIdx.x;
    const int col  = tid & 127;
    const int q    = tid >> 7;          // 0..3 -> t-range [32q, 32q+32)
    const int cg   = (tid >> 5) & 3;    // col-group 0..3
    const int tile = blockIdx.x;
    const int b    = blockIdx.y;
    const int d0   = tile * TD;
    const int t0   = q * 32;

    int dp = d0 - 3 + col;              // roll halo; only tile 0 wraps
    if (dp < 0) dp += DD;

    // --- Pre: 32 timestamp sign bits -> one word (all LDG latency here) ---
    unsigned tsbits = 0;
#pragma unroll
    for (int tt = 0; tt < 32; tt++)
        tsbits |= (__float_as_uint(timestamps_w[(t0 + tt) * DD + dp]) >> 31) << tt;

    // --- Pre: classify weights. Class-group q owns classes 3q..min(3q+2,9) ---
    const int n0 = 3 * q;               // 0,3,6,9 ; sizes 3/3/3/1
    float cw[3];
#pragma unroll
    for (int j = 0; j < 3; j++) {
        const int n = n0 + j;
        cw[j] = (n < NCLS && col < TD) ? classify_w[n * DD + d0 + col] : 0.f;
    }

    if (q == 0) {
        // --- Histogram for t = col (packed: 21 levels, <=32 per byte) ---
        uint4 z = make_uint4(0u, 0u, 0u, 0u);
        *(uint4*)&cnt_s[col * 8]     = z;
        *(uint4*)&cnt_s[col * 8 + 4] = z;
        const float4* xp = (const float4*)(x + (b * TT + col) * CC);
#pragma unroll
        for (int c4 = 0; c4 < CC / 4; c4++) {
            float4 v4 = xp[c4];
            float vv[4] = {v4.x, v4.y, v4.z, v4.w};
#pragma unroll
            for (int j = 0; j < 4; j++) {
                float v = (vv[j] / 20.0f) * 20.0f;   // mirrors reference fp exactly
                int iv = __float2int_rn(v);          // round half-to-even == jnp.round
                iv = iv < 0 ? 0 : (iv > 20 ? 20 : iv);
                cnt_s[col * 8 + (iv >> 2)] += 1u << ((iv & 3) * 8);
            }
        }
    } else if (q == 1) {
        // --- Pack column col's 21 signal signs as int8 bytes (+1 / -1) ---
        unsigned sw[6] = {0u, 0u, 0u, 0u, 0u, 0u};
#pragma unroll
        for (int l = 0; l < 21; l++) {
            unsigned neg  = __float_as_uint(signals_w[l * DD + dp]) >> 31;
            unsigned byte = neg ? 0xFFu : 0x01u;
            sw[l >> 2] |= byte << ((l & 3) * 8);
        }
#pragma unroll
        for (int l = 0; l < 6; l++) sw_s[l][col] = (int)sw[l];
    }
    __syncthreads();

    const int sp0 = sw_s[0][col], sp1 = sw_s[1][col], sp2 = sw_s[2][col];
    const int sp3 = sw_s[3][col], sp4 = sw_s[4][col], sp5 = sw_s[5][col];

    // --- Phase A: 32 t-rows via dp4a; pack 4 samples/word; 8 STS.32 ---
#pragma unroll
    for (int w = 0; w < 8; w++) {
        unsigned pk = 0;
#pragma unroll
        for (int u = 0; u < 4; u++) {
            const int t = t0 + 4 * w + u;
            uint4 ca = *(const uint4*)&cnt_s[t * 8];       // broadcast LDS
            uint2 cb = *(const uint2*)&cnt_s[t * 8 + 4];
            int a = 0;
            a = __dp4a((int)ca.x, sp0, a);
            a = __dp4a((int)ca.y, sp1, a);
            a = __dp4a((int)ca.z, sp2, a);
            a = __dp4a((int)ca.w, sp3, a);
            a = __dp4a((int)cb.x, sp4, a);
            a = __dp4a((int)cb.y, sp5, a);
            int v = ((tsbits >> (4 * w + u)) & 1u) ? -a : a;   // |v| <= 32
            pk |= ((unsigned)v & 0xFFu) << (8 * u);
        }
        ssw[col * CSTR + q * 8 + w] = pk;          // conflict-free (stride 33)
    }
    __syncthreads();

    // --- Phase B: window groups of 4; word loads + funnel align + extract ---
    int acc = 0;
    if (col < TD) {
        const int g0 = 8 * q;                      // groups [8q, 8q+8)
        unsigned c0 = ssw[(col + 0) * CSTR + g0];
        unsigned c1 = ssw[(col + 1) * CSTR + g0];
        unsigned c2 = ssw[(col + 2) * CSTR + g0];
        unsigned c3 = ssw[(col + 3) * CSTR + g0];
#pragma unroll
        for (int gg = 0; gg < 8; gg++) {
            const int g = g0 + gg;
            unsigned m0 = ssw[(col + 0) * CSTR + g + 1];   // word 32 = pad, only
            unsigned m1 = ssw[(col + 1) * CSTR + g + 1];   // feeds guarded-out windows
            unsigned m2 = ssw[(col + 2) * CSTR + g + 1];
            unsigned m3 = ssw[(col + 3) * CSTR + g + 1];
            const unsigned A0 = c0;
            const unsigned A1 = __funnelshift_r(c1, m1, 8);
            const unsigned A2 = __funnelshift_r(c2, m2, 16);
            const unsigned A3 = __funnelshift_r(c3, m3, 24);
#pragma unroll
            for (int j = 0; j < 4; j++) {
                const int i = 4 * g + j;                   // window index
                int b0 = (int)(A0 << ((3 - j) * 8)) >> 24; // signed byte j
                int b1 = (int)(A1 << ((3 - j) * 8)) >> 24;
                int b2 = (int)(A2 << ((3 - j) * 8)) >> 24;
                int b3 = (int)(A3 << ((3 - j) * 8)) >> 24;
                int p = b0 * b1 * b2 * b3;                 // exact, |p| <= 2^20
                if (i < NWIN) acc += p;
            }
            c0 = m0; c1 = m1; c2 = m2; c3 = m3;
        }
    }
    acc_s[q][col] = acc;
    __syncthreads();

    // --- Phase C: all 16 warps; <=3 classes each; shuffle reduce ---
    {
        const int at = acc_s[0][col] + acc_s[1][col] + acc_s[2][col] + acc_s[3][col];
        float val[3];
#pragma unroll
        for (int j = 0; j < 3; j++)
            val[j] = (at > 0) ? cw[j] : -cw[j];    // padded/inactive lanes hold 0
#pragma unroll
        for (int j = 0; j < 3; j++) {
#pragma unroll
            for (int off = 16; off > 0; off >>= 1)
                val[j] += __shfl_down_sync(0xffffffffu, val[j], off);
        }
        if ((tid & 31) == 0) {
#pragma unroll
            for (int j = 0; j < 3; j++) {
                const int n = n0 + j;
                if (n < NCLS) wsum2[n][cg] = val[j];
            }
        }
    }
    __syncthreads();
    if (tid < NCLS) {
        float s = wsum2[tid][0] + wsum2[tid][1] + wsum2[tid][2] + wsum2[tid][3];
        g_partial[(b * NTILES + tile) * NCLS + tid] = s;
    }

    // --- Deterministic last-block final reduction (fixed tile order) ---
    __threadfence();
    __syncthreads();
    if (tid == 0) {
        unsigned tk = atomicAdd(&g_ticket, 1u);
        last_flag = (tk == NBLK - 1);
    }
    __syncthreads();
    if (last_flag) {
        if (tid == 0) g_ticket = 0;        // reset for next graph replay
        __threadfence();
        if (tid < BB * NCLS) {
            int bb = tid / NCLS, n = tid % NCLS;
            float s = 0.f;
#pragma unroll 8
            for (int t2 = 0; t2 < NTILES; t2++)
                s += g_partial[(bb * NTILES + t2) * NCLS + n];
            out[bb * NCLS + n] = s;
        }
    }
}

extern "C" void kernel_launch(void* const* d_in, const int* in_sizes, int n_in,
                              void* d_out, int out_size) {
    const float* x            = (const float*)d_in[0];  // [4,128,32]
    const float* signals_w    = (const float*)d_in[1];  // [21,10000]
    // d_in[2] = channels_w : dead bind in reference, intentionally unused
    const float* timestamps_w = (const float*)d_in[3];  // [128,10000]
    const float* classify_w   = (const float*)d_in[4];  // [10,10000]
    float* out = (float*)d_out;                         // [4,10] fp32

    k_fused<<<dim3(NTILES, BB), 512>>>(x, signals_w, timestamps_w, classify_w, out);
}

// round 13
// speedup vs baseline: 1.2339x; 1.2339x over previous
#include <cuda_runtime.h>

#define DD     10000   // hypervector dimensions
#define TT     128     // time steps
#define CC     32      // channels
#define BB     4       // batch
#define NCLS   10
#define NWIN   125     // T - NGRAM + 1
#define TD     125     // d-tile per block (DD/TD = 80 exactly)
#define NTILES 80
#define NBLK   (NTILES * BB)   // 320
#define CSTR   33      // words per column (32 data + 1 pad; 33 % 32 == 1 -> conflict-free)

// Scratch (device globals — no allocation allowed; zero-initialized at load)
__device__ float    g_partial[BB * NTILES * NCLS];
__device__ unsigned g_ticket;

// ---------------------------------------------------------------------------
// Fused kernel, 512 threads = 16 warps: col = tid&127, q = tid>>7 (t-quarter).
// Column-major word-packed samples tile (stride 33 -> conflict-free LDS/STS.32).
// R13 deltas vs R12 (structure proven, now issue-bound):
//  * __launch_bounds__(512,3): cap 42 regs -> 3 blocks/SM -> 320 blocks in ONE
//    wave (148*3=444), occ ~70% (was 2 blocks/SM, 45%).
//  * classify_w load moved into phase C (frees 3 long-lived regs; one-time
//    post-barrier LDG, not on the hot path).
//  * pad word (word 32) of each column zeroed -> windows 125..127 contribute
//    exact 0 -> phase B runs 8 unguarded groups for every q (no ISETP/pred).
//  * phase A packs bytes with PRMT (__byte_perm), 1 instr per byte.
// ---------------------------------------------------------------------------
__global__ __launch_bounds__(512, 3) void k_fused(
    const float* __restrict__ x,
    const float* __restrict__ signals_w,
    const float* __restrict__ timestamps_w,
    const float* __restrict__ classify_w,
    float* __restrict__ out)
{
    __shared__ __align__(16) unsigned cnt_s[TT * 8];   // 4 KB packed histograms
    __shared__ int sw_s[6][128];                       // 3 KB packed signal signs
    __shared__ unsigned ssw[128 * CSTR];               // 16.9 KB word-packed samples
    __shared__ int   acc_s[4][128];                    // window-quarter partials
    __shared__ float wsum2[NCLS][4];                   // per-(class, col-group)
    __shared__ int   last_flag;

    const int tid  = threadIdx.x;
    const int col  = tid & 127;
    const int q    = tid >> 7;          // 0..3 -> t-range [32q, 32q+32)
    const int cg   = (tid >> 5) & 3;    // col-group 0..3
    const int tile = blockIdx.x;
    const int b    = blockIdx.y;
    const int d0   = tile * TD;
    const int t0   = q * 32;

    int dp = d0 - 3 + col;              // roll halo; only tile 0 wraps
    if (dp < 0) dp += DD;

    // --- Pre: 32 timestamp sign bits -> one word (all LDG latency here) ---
    unsigned tsbits = 0;
#pragma unroll
    for (int tt = 0; tt < 32; tt++)
        tsbits |= (__float_as_uint(timestamps_w[(t0 + tt) * DD + dp]) >> 31) << tt;

    if (q == 0) {
        // --- Histogram for t = col (packed: 21 levels, <=32 per byte) ---
        uint4 z = make_uint4(0u, 0u, 0u, 0u);
        *(uint4*)&cnt_s[col * 8]     = z;
        *(uint4*)&cnt_s[col * 8 + 4] = z;
        const float4* xp = (const float4*)(x + (b * TT + col) * CC);
#pragma unroll
        for (int c4 = 0; c4 < CC / 4; c4++) {
            float4 v4 = xp[c4];
            float vv[4] = {v4.x, v4.y, v4.z, v4.w};
#pragma unroll
            for (int j = 0; j < 4; j++) {
                float v = (vv[j] / 20.0f) * 20.0f;   // mirrors reference fp exactly
                int iv = __float2int_rn(v);          // round half-to-even == jnp.round
                iv = iv < 0 ? 0 : (iv > 20 ? 20 : iv);
                cnt_s[col * 8 + (iv >> 2)] += 1u << ((iv & 3) * 8);
            }
        }
    } else if (q == 1) {
        // --- Pack column col's 21 signal signs as int8 bytes (+1 / -1) ---
        unsigned sw[6] = {0u, 0u, 0u, 0u, 0u, 0u};
#pragma unroll
        for (int l = 0; l < 21; l++) {
            unsigned neg  = __float_as_uint(signals_w[l * DD + dp]) >> 31;
            unsigned byte = neg ? 0xFFu : 0x01u;
            sw[l >> 2] |= byte << ((l & 3) * 8);
        }
#pragma unroll
        for (int l = 0; l < 6; l++) sw_s[l][col] = (int)sw[l];
    } else if (q == 2) {
        ssw[col * CSTR + 32] = 0u;      // zero pad word: windows >=125 vanish
    }
    __syncthreads();

    const int sp0 = sw_s[0][col], sp1 = sw_s[1][col], sp2 = sw_s[2][col];
    const int sp3 = sw_s[3][col], sp4 = sw_s[4][col], sp5 = sw_s[5][col];

    // --- Phase A: 32 t-rows via dp4a; PRMT byte pack; 8 conflict-free STS.32 ---
#pragma unroll
    for (int w = 0; w < 8; w++) {
        unsigned pk = 0;
#pragma unroll
        for (int u = 0; u < 4; u++) {
            const int t = t0 + 4 * w + u;
            uint4 ca = *(const uint4*)&cnt_s[t * 8];       // broadcast LDS
            uint2 cb = *(const uint2*)&cnt_s[t * 8 + 4];
            int a = 0;
            a = __dp4a((int)ca.x, sp0, a);
            a = __dp4a((int)ca.y, sp1, a);
            a = __dp4a((int)ca.z, sp2, a);
            a = __dp4a((int)ca.w, sp3, a);
            a = __dp4a((int)cb.x, sp4, a);
            a = __dp4a((int)cb.y, sp5, a);
            int m = (int)(tsbits << (31 - (4 * w + u))) >> 31;  // 0 or -1
            int v = (a ^ m) - m;                                 // +-a, |v| <= 32
            // insert low byte of v into byte u of pk (PRMT)
            const unsigned sel = (u == 0) ? 0x3214u : (u == 1) ? 0x3240u
                               : (u == 2) ? 0x3410u : 0x4210u;
            pk = __byte_perm(pk, (unsigned)v, sel);
        }
        ssw[col * CSTR + q * 8 + w] = pk;          // conflict-free (stride 33)
    }
    __syncthreads();

    // --- Phase B: 8 unguarded window groups; word loads + funnel + extract ---
    int acc = 0;
    if (col < TD) {
        const int g0 = 8 * q;                      // groups [8q, 8q+8)
        unsigned c0 = ssw[(col + 0) * CSTR + g0];
        unsigned c1 = ssw[(col + 1) * CSTR + g0];
        unsigned c2 = ssw[(col + 2) * CSTR + g0];
        unsigned c3 = ssw[(col + 3) * CSTR + g0];
#pragma unroll
        for (int gg = 0; gg < 8; gg++) {
            const int g = g0 + gg;
            unsigned m0 = ssw[(col + 0) * CSTR + g + 1];
            unsigned m1 = ssw[(col + 1) * CSTR + g + 1];
            unsigned m2 = ssw[(col + 2) * CSTR + g + 1];
            unsigned m3 = ssw[(col + 3) * CSTR + g + 1];
            const unsigned A0 = c0;
            const unsigned A1 = __funnelshift_r(c1, m1, 8);
            const unsigned A2 = __funnelshift_r(c2, m2, 16);
            const unsigned A3 = __funnelshift_r(c3, m3, 24);
#pragma unroll
            for (int j = 0; j < 4; j++) {
                int b0 = (int)(A0 << ((3 - j) * 8)) >> 24; // signed byte j
                int b1 = (int)(A1 << ((3 - j) * 8)) >> 24;
                int b2 = (int)(A2 << ((3 - j) * 8)) >> 24;
                int b3 = (int)(A3 << ((3 - j) * 8)) >> 24;
                acc += b0 * b1 * b2 * b3;                  // exact; pad rows -> 0
            }
            c0 = m0; c1 = m1; c2 = m2; c3 = m3;
        }
    }
    acc_s[q][col] = acc;
    __syncthreads();

    // --- Phase C: all 16 warps; <=3 classes each; load cw here (off hot path) ---
    {
        const int n0 = 3 * q;               // class split 3/3/3/1 over q
        const int at = acc_s[0][col] + acc_s[1][col] + acc_s[2][col] + acc_s[3][col];
        float val[3];
#pragma unroll
        for (int j = 0; j < 3; j++) {
            const int n = n0 + j;
            float wv = (n < NCLS && col < TD) ? classify_w[n * DD + d0 + col] : 0.f;
            val[j] = (at > 0) ? wv : -wv;   // padded/inactive lanes hold 0
        }
#pragma unroll
        for (int j = 0; j < 3; j++) {
#pragma unroll
            for (int off = 16; off > 0; off >>= 1)
                val[j] += __shfl_down_sync(0xffffffffu, val[j], off);
        }
        if ((tid & 31) == 0) {
#pragma unroll
            for (int j = 0; j < 3; j++) {
                const int n = n0 + j;
                if (n < NCLS) wsum2[n][cg] = val[j];
            }
        }
    }
    __syncthreads();
    if (tid < NCLS) {
        float s = wsum2[tid][0] + wsum2[tid][1] + wsum2[tid][2] + wsum2[tid][3];
        g_partial[(b * NTILES + tile) * NCLS + tid] = s;
    }

    // --- Deterministic last-block final reduction (fixed tile order) ---
    __threadfence();
    __syncthreads();
    if (tid == 0) {
        unsigned tk = atomicAdd(&g_ticket, 1u);
        last_flag = (tk == NBLK - 1);
    }
    __syncthreads();
    if (last_flag) {
        if (tid == 0) g_ticket = 0;        // reset for next graph replay
        __threadfence();
        if (tid < BB * NCLS) {
            int bb = tid / NCLS, n = tid % NCLS;
            float s = 0.f;
#pragma unroll 8
            for (int t2 = 0; t2 < NTILES; t2++)
                s += g_partial[(bb * NTILES + t2) * NCLS + n];
            out[bb * NCLS + n] = s;
        }
    }
}

extern "C" void kernel_launch(void* const* d_in, const int* in_sizes, int n_in,
                              void* d_out, int out_size) {
    const float* x            = (const float*)d_in[0];  // [4,128,32]
    const float* signals_w    = (const float*)d_in[1];  // [21,10000]
    // d_in[2] = channels_w : dead bind in reference, intentionally unused
    const float* timestamps_w = (const float*)d_in[3];  // [128,10000]
    const float* classify_w   = (const float*)d_in[4];  // [10,10000]
    float* out = (float*)d_out;                         // [4,10] fp32

    k_fused<<<dim3(NTILES, BB), 512>>>(x, signals_w, timestamps_w, classify_w, out);
}

// round 16
// speedup vs baseline: 1.3584x; 1.1009x over previous
#include <cuda_runtime.h>

#define DD     10000   // hypervector dimensions
#define TT     128     // time steps
#define CC     32      // channels
#define BB     4       // batch
#define NCLS   10
#define NWIN   125     // T - NGRAM + 1
#define TD     136     // d-tile per block (74 * 136 = 10064 covers 10000)
#define NTILES 74
#define NBLK   (NTILES * BB)   // 296 = 2 * 148 -> exactly 2 blocks per SM
#define NCOLS  160     // 5 col-warps (TD + 3 halo = 139 used)
#define CSTR   33      // words per column (32 data + 1 pad; 33 % 32 == 1 -> conflict-free)

// Scratch (device globals — no allocation allowed; zero-initialized at load)
__device__ float    g_partial[BB * NTILES * NCLS];
__device__ unsigned g_ticket;

// ---------------------------------------------------------------------------
// Fused kernel, 640 threads = 20 warps = 4 t-quarters (q) x 5 col-warps (cw).
// col = cw*32+lane in [0,160); d-column dp = (d0-3+col) mod DD. Tile covers
// outputs d0..d0+135 (last tile partial; guarded by owns). Samples tile is
// column-major word-packed (stride 33 words -> conflict-free 32-bit LDS/STS).
// R16 delta vs R15: phase-B signed-byte extraction reverted to the verified
// shl/asr pair (R15's PRMT sign-replicate mode corrupted signs -> rel_err 1.36).
// Retained from R15: balanced grid 296 = exactly 2 blocks on every SM.
// ---------------------------------------------------------------------------
__global__ __launch_bounds__(640, 2) void k_fused(
    const float* __restrict__ x,
    const float* __restrict__ signals_w,
    const float* __restrict__ timestamps_w,
    const float* __restrict__ classify_w,
    float* __restrict__ out)
{
    __shared__ __align__(16) unsigned cnt_s[TT * 8];   // 4 KB packed histograms
    __shared__ int sw_s[6][NCOLS];                     // packed signal signs
    __shared__ unsigned ssw[NCOLS * CSTR];             // 21.1 KB word-packed samples
    __shared__ int   acc_s[4][NCOLS];                  // window-quarter partials
    __shared__ float wsum2[NCLS][5];                   // per-(class, col-warp)
    __shared__ int   last_flag;

    const int tid  = threadIdx.x;
    const int w    = tid >> 5;          // warp 0..19
    const int lane = tid & 31;
    const int cw   = w % 5;             // col-warp 0..4
    const int q    = w / 5;             // t-quarter 0..3 -> t in [32q, 32q+32)
    const int col  = cw * 32 + lane;    // 0..159
    const int tile = blockIdx.x;
    const int b    = blockIdx.y;
    const int d0   = tile * TD;
    const int t0   = q * 32;

    int dp = d0 - 3 + col;              // roll column (mod DD)
    if (dp < 0)   dp += DD;
    if (dp >= DD) dp -= DD;

    // --- Pre: 32 timestamp sign bits -> one word (all LDG latency here) ---
    unsigned tsbits = 0;
#pragma unroll
    for (int tt = 0; tt < 32; tt++)
        tsbits |= (__float_as_uint(timestamps_w[(t0 + tt) * DD + dp]) >> 31) << tt;

    if (q == 0) {
        if (col < TT) {
            // --- Histogram for t = col (packed: 21 levels, <=32 per byte) ---
            uint4 z = make_uint4(0u, 0u, 0u, 0u);
            *(uint4*)&cnt_s[col * 8]     = z;
            *(uint4*)&cnt_s[col * 8 + 4] = z;
            const float4* xp = (const float4*)(x + (b * TT + col) * CC);
#pragma unroll
            for (int c4 = 0; c4 < CC / 4; c4++) {
                float4 v4 = xp[c4];
                float vv[4] = {v4.x, v4.y, v4.z, v4.w};
#pragma unroll
                for (int j = 0; j < 4; j++) {
                    float v = (vv[j] / 20.0f) * 20.0f;   // mirrors reference fp
                    int iv = __float2int_rn(v);          // round half-to-even
                    iv = iv < 0 ? 0 : (iv > 20 ? 20 : iv);
                    cnt_s[col * 8 + (iv >> 2)] += 1u << ((iv & 3) * 8);
                }
            }
        }
    } else if (q == 1) {
        // --- Pack column col's 21 signal signs as int8 bytes (+1 / -1) ---
        unsigned sw[6] = {0u, 0u, 0u, 0u, 0u, 0u};
#pragma unroll
        for (int l = 0; l < 21; l++) {
            unsigned neg  = __float_as_uint(signals_w[l * DD + dp]) >> 31;
            unsigned byte = neg ? 0xFFu : 0x01u;
            sw[l >> 2] |= byte << ((l & 3) * 8);
        }
#pragma unroll
        for (int l = 0; l < 6; l++) sw_s[l][col] = (int)sw[l];
    } else if (q == 2) {
        ssw[col * CSTR + 32] = 0u;      // zero pad word: windows >=125 vanish
    }
    __syncthreads();

    const int sp0 = sw_s[0][col], sp1 = sw_s[1][col], sp2 = sw_s[2][col];
    const int sp3 = sw_s[3][col], sp4 = sw_s[4][col], sp5 = sw_s[5][col];

    // --- Phase A: 32 t-rows via dp4a; PRMT byte pack; 8 conflict-free STS.32 ---
#pragma unroll
    for (int ww = 0; ww < 8; ww++) {
        unsigned pk = 0;
#pragma unroll
        for (int u = 0; u < 4; u++) {
            const int t = t0 + 4 * ww + u;
            uint4 ca = *(const uint4*)&cnt_s[t * 8];       // broadcast LDS
            uint2 cb = *(const uint2*)&cnt_s[t * 8 + 4];
            int a = 0;
            a = __dp4a((int)ca.x, sp0, a);
            a = __dp4a((int)ca.y, sp1, a);
            a = __dp4a((int)ca.z, sp2, a);
            a = __dp4a((int)ca.w, sp3, a);
            a = __dp4a((int)cb.x, sp4, a);
            a = __dp4a((int)cb.y, sp5, a);
            int m = (int)(tsbits << (31 - (4 * ww + u))) >> 31;  // 0 or -1
            int v = (a ^ m) - m;                                 // +-a, |v| <= 32
            const unsigned sel = (u == 0) ? 0x3214u : (u == 1) ? 0x3240u
                               : (u == 2) ? 0x3410u : 0x4210u;
            pk = __byte_perm(pk, (unsigned)v, sel);     // insert byte u (verified R13)
        }
        ssw[col * CSTR + q * 8 + ww] = pk;              // conflict-free (stride 33)
    }
    __syncthreads();

    // --- Phase B: 8 unguarded window groups; shl/asr signed-byte extracts ---
    int acc = 0;
    if (col < TD) {                    // halo cols 136..159 skip
        const int g0 = 8 * q;          // groups [8q, 8q+8), windows [32q, 32q+32)
        unsigned c0 = ssw[(col + 0) * CSTR + g0];
        unsigned c1 = ssw[(col + 1) * CSTR + g0];
        unsigned c2 = ssw[(col + 2) * CSTR + g0];
        unsigned c3 = ssw[(col + 3) * CSTR + g0];
#pragma unroll
        for (int gg = 0; gg < 8; gg++) {
            const int g = g0 + gg;
            unsigned m0 = ssw[(col + 0) * CSTR + g + 1];
            unsigned m1 = ssw[(col + 1) * CSTR + g + 1];
            unsigned m2 = ssw[(col + 2) * CSTR + g + 1];
            unsigned m3 = ssw[(col + 3) * CSTR + g + 1];
            const unsigned A0 = c0;
            const unsigned A1 = __funnelshift_r(c1, m1, 8);
            const unsigned A2 = __funnelshift_r(c2, m2, 16);
            const unsigned A3 = __funnelshift_r(c3, m3, 24);
#pragma unroll
            for (int j = 0; j < 4; j++) {
                int b0 = (int)(A0 << ((3 - j) * 8)) >> 24;   // signed byte j
                int b1 = (int)(A1 << ((3 - j) * 8)) >> 24;
                int b2 = (int)(A2 << ((3 - j) * 8)) >> 24;
                int b3 = (int)(A3 << ((3 - j) * 8)) >> 24;
                acc += b0 * b1 * b2 * b3;               // exact; pad rows -> 0
            }
            c0 = m0; c1 = m1; c2 = m2; c3 = m3;
        }
    }
    acc_s[q][col] = acc;
    __syncthreads();

    // --- Phase C: all 20 warps; class split 3/3/3/1 over q; col over cw ---
    {
        const int n0 = 3 * q;
        const int at = acc_s[0][col] + acc_s[1][col] + acc_s[2][col] + acc_s[3][col];
        const bool owns = (col < TD) && (d0 + col < DD);   // last tile partial
        float val[3];
#pragma unroll
        for (int j = 0; j < 3; j++) {
            const int n = n0 + j;
            float wv = (n < NCLS && owns) ? classify_w[n * DD + d0 + col] : 0.f;
            val[j] = (at > 0) ? wv : -wv;   // non-owning lanes contribute 0
        }
#pragma unroll
        for (int j = 0; j < 3; j++) {
#pragma unroll
            for (int off = 16; off > 0; off >>= 1)
                val[j] += __shfl_down_sync(0xffffffffu, val[j], off);
        }
        if (lane == 0) {
#pragma unroll
            for (int j = 0; j < 3; j++) {
                const int n = n0 + j;
                if (n < NCLS) wsum2[n][cw] = val[j];
            }
        }
    }
    __syncthreads();
    if (tid < NCLS) {
        float s = wsum2[tid][0] + wsum2[tid][1] + wsum2[tid][2]
                + wsum2[tid][3] + wsum2[tid][4];
        g_partial[(b * NTILES + tile) * NCLS + tid] = s;
    }

    // --- Deterministic last-block final reduction (fixed tile order) ---
    __threadfence();
    __syncthreads();
    if (tid == 0) {
        unsigned tk = atomicAdd(&g_ticket, 1u);
        last_flag = (tk == NBLK - 1);
    }
    __syncthreads();
    if (last_flag) {
        if (tid == 0) g_ticket = 0;        // reset for next graph replay
        __threadfence();
        if (tid < BB * NCLS) {
            int bb = tid / NCLS, n = tid % NCLS;
            float s = 0.f;
#pragma unroll 8
            for (int t2 = 0; t2 < NTILES; t2++)
                s += g_partial[(bb * NTILES + t2) * NCLS + n];
            out[bb * NCLS + n] = s;
        }
    }
}

extern "C" void kernel_launch(void* const* d_in, const int* in_sizes, int n_in,
                              void* d_out, int out_size) {
    const float* x            = (const float*)d_in[0];  // [4,128,32]
    const float* signals_w    = (const float*)d_in[1];  // [21,10000]
    // d_in[2] = channels_w : dead bind in reference, intentionally unused
    const float* timestamps_w = (const float*)d_in[3];  // [128,10000]
    const float* classify_w   = (const float*)d_in[4];  // [10,10000]
    float* out = (float*)d_out;                         // [4,10] fp32

    k_fused<<<dim3(NTILES, BB), 640>>>(x, signals_w, timestamps_w, classify_w, out);
}